// round 10
// baseline (speedup 1.0000x reference)
#include <cuda_runtime.h>
#include <cuda_fp16.h>
#include <cstdint>

#define NE 8
#define HID 2048
#define INT_DIM 2048
#define NTOK 4096
#define TK 8192
#define N1 4096

#define BKH 64            // k-halves per stage (128B rows)
#define BLKM 256          // rows per CTA
#define LDS_H 72          // halves per smem row (64 data + 8 pad = 144B)
#define A_TILE_BYTES (BLKM * LDS_H * 2)     // 36864
#define B_OFF        A_TILE_BYTES
#define B_TILE_BYTES (128 * LDS_H * 2)      // 18432
#define STAGE_BYTES  (A_TILE_BYTES + B_TILE_BYTES)  // 55296
#define NSTAGE 4
#define SMEM_DYN (NSTAGE * STAGE_BYTES)     // 221184

// ---------------- scratch ----------------
__device__ int    d_off[NE + 1];
__device__ int    d_row_slot[TK];
__device__ int    d_row_of_slot[TK];
__device__ __half d_hid16[(size_t)NTOK * HID];
__device__ __half d_w1h[(size_t)NE * N1 * HID];
__device__ __half d_w2h[(size_t)NE * HID * INT_DIM];
__device__ __half d_act16[(size_t)TK * INT_DIM];

// ---------------- helpers ----------------
__device__ __forceinline__ uint32_t smem_u32(const void* p) {
    uint32_t a;
    asm("{ .reg .u64 t; cvta.to.shared.u64 t, %1; cvt.u32.u64 %0, t; }" : "=r"(a) : "l"(p));
    return a;
}
__device__ __forceinline__ void ldsm4(uint32_t& r0, uint32_t& r1, uint32_t& r2, uint32_t& r3,
                                      uint32_t addr) {
    asm volatile("ldmatrix.sync.aligned.m8n8.x4.shared.b16 {%0,%1,%2,%3}, [%4];"
                 : "=r"(r0), "=r"(r1), "=r"(r2), "=r"(r3) : "r"(addr));
}
__device__ __forceinline__ void mma16816(float& c0, float& c1, float& c2, float& c3,
                                         uint32_t a0, uint32_t a1, uint32_t a2, uint32_t a3,
                                         uint32_t b0, uint32_t b1) {
    asm volatile("mma.sync.aligned.m16n8k16.row.col.f32.f16.f16.f32 "
                 "{%0,%1,%2,%3}, {%4,%5,%6,%7}, {%8,%9}, {%0,%1,%2,%3};"
                 : "+f"(c0), "+f"(c1), "+f"(c2), "+f"(c3)
                 : "r"(a0), "r"(a1), "r"(a2), "r"(a3), "r"(b0), "r"(b1));
}
__device__ __forceinline__ void cp16(uint32_t dst, const void* src, bool pred) {
    int sz = pred ? 16 : 0;
    asm volatile("cp.async.cg.shared.global [%0], [%1], 16, %2;"
                 :: "r"(dst), "l"(src), "r"(sz) : "memory");
}
#define CP_COMMIT() asm volatile("cp.async.commit_group;" ::: "memory")
#define CP_WAIT(n)  asm volatile("cp.async.wait_group %0;" :: "n"(n) : "memory")

// ---------------- fp32 -> fp16 conversion (streaming reads) ----------------
__global__ void cvt_kernel(const float* __restrict__ src, __half* __restrict__ dst, int n4) {
    int i = blockIdx.x * blockDim.x + threadIdx.x;
    int stride = gridDim.x * blockDim.x;
    for (; i < n4; i += stride) {
        float4 v = __ldcs((const float4*)(src + (size_t)i * 4));
        __half2 h01 = __floats2half2_rn(v.x, v.y);
        __half2 h23 = __floats2half2_rn(v.z, v.w);
        uint2 u;
        u.x = *(uint32_t*)&h01;
        u.y = *(uint32_t*)&h23;
        *(uint2*)(dst + (size_t)i * 4) = u;
    }
}

// ---------------- zero output ----------------
__global__ void zero_kernel(float* __restrict__ out, int n4) {
    int i = blockIdx.x * blockDim.x + threadIdx.x;
    int stride = gridDim.x * blockDim.x;
    for (; i < n4; i += stride)
        *(float4*)(out + (size_t)i * 4) = make_float4(0.f, 0.f, 0.f, 0.f);
}

// ---------------- routing ----------------
__global__ void route_kernel(const int* __restrict__ topk) {
    __shared__ int s_cnt[NE];
    __shared__ int s_pos[NE];
    int tid = threadIdx.x;
    if (tid < NE) s_cnt[tid] = 0;
    __syncthreads();
    for (int s = tid; s < TK; s += blockDim.x)
        atomicAdd(&s_cnt[topk[s]], 1);
    __syncthreads();
    if (tid == 0) {
        int a = 0;
        for (int e = 0; e < NE; e++) { d_off[e] = a; s_pos[e] = a; a += s_cnt[e]; }
        d_off[NE] = a;
    }
    __syncthreads();
    for (int s = tid; s < TK; s += blockDim.x) {
        int e = topk[s];
        int r = atomicAdd(&s_pos[e], 1);
        d_row_slot[r]    = s;
        d_row_of_slot[s] = r;
    }
}

// ---------------- grouped GEMM: cp.async 4-stage, all-fp16 operands ----------------
// PHASE 1: A = d_hid16 (gathered); B rows = [gate nt..nt+63 | up nt..nt+63] of d_w1h
//          epilogue: SwiGLU * routing weight -> d_act16; full K=2048
// PHASE 2: A = d_act16; B = d_w2h rows nt..nt+127; split-K x2 (blockIdx.x&1 picks
//          K half of 1024); epilogue: atomicAdd into out[token]
template <int PHASE>
__global__ __launch_bounds__(512, 1) void moe_mma(const float* __restrict__ wts,
                                                  float* __restrict__ out) {
    const int e   = blockIdx.z;
    const int off = d_off[e];
    const int cnt = d_off[e + 1] - off;
    const int rt  = blockIdx.y * BLKM;
    if (rt >= cnt) return;
    int nt, koff;
    if (PHASE == 1) { nt = blockIdx.x * 64;          koff = 0; }
    else            { nt = (blockIdx.x >> 1) * 128;  koff = (blockIdx.x & 1) * (HID / 2); }

    extern __shared__ __align__(16) char smem_raw[];
    const uint32_t sb = smem_u32(smem_raw);

    const int tid  = threadIdx.x;
    const int wid  = tid >> 5, lane = tid & 31;
    const int wm   = wid >> 2;
    const int wn   = wid & 3;

    const int Krow = HID;                                  // row stride (halves)
    const int NCH  = (PHASE == 1 ? HID : HID / 2) / BKH;   // 32 / 16
    const __half* Wh = (PHASE == 1)
        ? d_w1h + (size_t)e * N1 * HID
        : d_w2h + (size_t)e * HID * INT_DIM;

    // ---- cp.async assignments ----
    const __half* aSrc[4]; bool aval[4]; uint32_t aDst[4];
    #pragma unroll
    for (int i = 0; i < 4; i++) {
        int chunk = i * 512 + tid;
        int row = chunk >> 3, c16 = chunk & 7;
        int rg = rt + row;
        aval[i] = rg < cnt;
        aDst[i] = (uint32_t)(row * (LDS_H * 2) + c16 * 16);
        if (PHASE == 1) {
            int tok = aval[i] ? (d_row_slot[off + rg] >> 1) : 0;
            aSrc[i] = d_hid16 + (size_t)tok * HID + c16 * 8;
        } else {
            aSrc[i] = d_act16 + (size_t)(off + (aval[i] ? rg : 0)) * INT_DIM + koff + c16 * 8;
        }
    }
    const __half* bSrc[2]; uint32_t bDst[2];
    #pragma unroll
    for (int i = 0; i < 2; i++) {
        int chunk = i * 512 + tid;
        int row = chunk >> 3, c16 = chunk & 7;
        int grow;
        if (PHASE == 1) grow = (row < 64) ? (nt + row) : (INT_DIM + nt + (row - 64));
        else            grow = nt + row;
        bDst[i] = (uint32_t)(B_OFF + row * (LDS_H * 2) + c16 * 16);
        bSrc[i] = Wh + (size_t)grow * Krow + koff + c16 * 8;
    }

    // ldmatrix byte offsets (kk = 0)
    int aOff[4], bOff[2];
    #pragma unroll
    for (int mi = 0; mi < 4; mi++)
        aOff[mi] = ((wm * 64 + mi * 16 + (lane & 15)) * LDS_H) * 2 + (lane >> 4) * 16;
    #pragma unroll
    for (int g = 0; g < 2; g++)
        bOff[g] = B_OFF + ((wn * 32 + g * 16 + ((lane >> 4) & 1) * 8 + (lane & 7)) * LDS_H) * 2
                  + ((lane >> 3) & 1) * 16;

    float acc[4][4][4];
    #pragma unroll
    for (int mi = 0; mi < 4; mi++)
        #pragma unroll
        for (int ni = 0; ni < 4; ni++)
            #pragma unroll
            for (int q = 0; q < 4; q++) acc[mi][ni][q] = 0.f;

    #define ISSUE(ks) do {                                              \
        uint32_t _base = sb + ((ks) % NSTAGE) * STAGE_BYTES;            \
        int _ko = (ks) * BKH;                                           \
        _Pragma("unroll")                                               \
        for (int _i = 0; _i < 4; _i++)                                  \
            cp16(_base + aDst[_i], aSrc[_i] + _ko, aval[_i]);           \
        _Pragma("unroll")                                               \
        for (int _i = 0; _i < 2; _i++)                                  \
            cp16(_base + bDst[_i], bSrc[_i] + _ko, true);               \
        CP_COMMIT();                                                    \
    } while (0)

    ISSUE(0);
    ISSUE(1);
    ISSUE(2);

    for (int c = 0; c < NCH; c++) {
        CP_WAIT(2);
        __syncthreads();
        if (c + 3 < NCH) ISSUE(c + 3); else CP_COMMIT();

        const uint32_t st = sb + (c % NSTAGE) * STAGE_BYTES;
        #pragma unroll
        for (int kk = 0; kk < 4; kk++) {
            const int kb = kk * 32;
            uint32_t a[4][4], b[4][2];
            #pragma unroll
            for (int mi = 0; mi < 4; mi++)
                ldsm4(a[mi][0], a[mi][1], a[mi][2], a[mi][3], st + aOff[mi] + kb);
            #pragma unroll
            for (int g = 0; g < 2; g++)
                ldsm4(b[2 * g][0], b[2 * g][1], b[2 * g + 1][0], b[2 * g + 1][1],
                      st + bOff[g] + kb);
            #pragma unroll
            for (int mi = 0; mi < 4; mi++)
                #pragma unroll
                for (int ni = 0; ni < 4; ni++)
                    mma16816(acc[mi][ni][0], acc[mi][ni][1], acc[mi][ni][2], acc[mi][ni][3],
                             a[mi][0], a[mi][1], a[mi][2], a[mi][3],
                             b[ni][0], b[ni][1]);
        }
    }
    #undef ISSUE
    CP_WAIT(0);
    __syncthreads();  // all reads done before smem reuse in epilogue

    // ---- epilogue ----
    if (PHASE == 1) {
        float* exch = (float*)smem_raw;  // 256 x 66 fp32 = 67584 <= SMEM_DYN
        const int EP = 66;
        if (wn < 2) {
            #pragma unroll
            for (int mi = 0; mi < 4; mi++) {
                int row0 = wm * 64 + mi * 16 + (lane >> 2);
                #pragma unroll
                for (int ni = 0; ni < 4; ni++) {
                    int col = wn * 32 + ni * 8 + 2 * (lane & 3);
                    float g0 = acc[mi][ni][0], g1 = acc[mi][ni][1];
                    float g2 = acc[mi][ni][2], g3 = acc[mi][ni][3];
                    exch[row0 * EP + col]           = g0 / (1.f + __expf(-g0));
                    exch[row0 * EP + col + 1]       = g1 / (1.f + __expf(-g1));
                    exch[(row0 + 8) * EP + col]     = g2 / (1.f + __expf(-g2));
                    exch[(row0 + 8) * EP + col + 1] = g3 / (1.f + __expf(-g3));
                }
            }
        }
        __syncthreads();
        if (wn >= 2) {
            #pragma unroll
            for (int mi = 0; mi < 4; mi++) {
                int row0 = wm * 64 + mi * 16 + (lane >> 2);
                int rg0 = rt + row0, rg1 = rg0 + 8;
                bool v0 = rg0 < cnt, v1 = rg1 < cnt;
                float w0 = v0 ? wts[d_row_slot[off + rg0]] : 0.f;
                float w1 = v1 ? wts[d_row_slot[off + rg1]] : 0.f;
                #pragma unroll
                for (int ni = 0; ni < 4; ni++) {
                    int col = (wn - 2) * 32 + ni * 8 + 2 * (lane & 3);
                    float s0 = exch[row0 * EP + col];
                    float s1 = exch[row0 * EP + col + 1];
                    float s2 = exch[(row0 + 8) * EP + col];
                    float s3 = exch[(row0 + 8) * EP + col + 1];
                    float a0 = s0 * acc[mi][ni][0] * w0;
                    float a1 = s1 * acc[mi][ni][1] * w0;
                    float a2 = s2 * acc[mi][ni][2] * w1;
                    float a3 = s3 * acc[mi][ni][3] * w1;
                    if (v0) {
                        __half2 h = __floats2half2_rn(a0, a1);
                        *(uint32_t*)&d_act16[(size_t)(off + rg0) * INT_DIM + nt + col] =
                            *(uint32_t*)&h;
                    }
                    if (v1) {
                        __half2 h = __floats2half2_rn(a2, a3);
                        *(uint32_t*)&d_act16[(size_t)(off + rg1) * INT_DIM + nt + col] =
                            *(uint32_t*)&h;
                    }
                }
            }
        }
    } else {
        #pragma unroll
        for (int mi = 0; mi < 4; mi++) {
            int row0 = wm * 64 + mi * 16 + (lane >> 2);
            int rg0 = rt + row0, rg1 = rg0 + 8;
            bool v0 = rg0 < cnt, v1 = rg1 < cnt;
            int t0 = v0 ? (d_row_slot[off + rg0] >> 1) : 0;
            int t1 = v1 ? (d_row_slot[off + rg1] >> 1) : 0;
            #pragma unroll
            for (int ni = 0; ni < 4; ni++) {
                int col = nt + wn * 32 + ni * 8 + 2 * (lane & 3);
                if (v0) {
                    float* p = out + (size_t)t0 * HID + col;
                    atomicAdd(p,     acc[mi][ni][0]);
                    atomicAdd(p + 1, acc[mi][ni][1]);
                }
                if (v1) {
                    float* p = out + (size_t)t1 * HID + col;
                    atomicAdd(p,     acc[mi][ni][2]);
                    atomicAdd(p + 1, acc[mi][ni][3]);
                }
            }
        }
    }
}

// ---------------- launcher ----------------
extern "C" void kernel_launch(void* const* d_in, const int* in_sizes, int n_in,
                              void* d_out, int out_size) {
    const float* hidden = (const float*)d_in[0];
    const int*   topk   = (const int*)  d_in[1];
    const float* wts    = (const float*)d_in[2];
    const float* gup    = (const float*)d_in[3];
    const float* downW  = (const float*)d_in[4];
    float* out = (float*)d_out;

    cudaFuncSetAttribute(moe_mma<1>, cudaFuncAttributeMaxDynamicSharedMemorySize, SMEM_DYN);
    cudaFuncSetAttribute(moe_mma<2>, cudaFuncAttributeMaxDynamicSharedMemorySize, SMEM_DYN);

    __half* hid16p; cudaGetSymbolAddress((void**)&hid16p, d_hid16);
    __half* w1p;    cudaGetSymbolAddress((void**)&w1p,    d_w1h);
    __half* w2p;    cudaGetSymbolAddress((void**)&w2p,    d_w2h);

    // one-time side stream + events (host resources only; no device memory)
    static cudaStream_t s_side = nullptr;
    static cudaEvent_t ev_fork = nullptr, ev_route = nullptr, ev_join = nullptr;
    if (s_side == nullptr) {
        cudaStreamCreateWithFlags(&s_side, cudaStreamNonBlocking);
        cudaEventCreateWithFlags(&ev_fork,  cudaEventDisableTiming);
        cudaEventCreateWithFlags(&ev_route, cudaEventDisableTiming);
        cudaEventCreateWithFlags(&ev_join,  cudaEventDisableTiming);
    }

    // fork: side stream does route + w2 cvt + zero (only needed by GEMM2 / GEMM1-start)
    cudaEventRecord(ev_fork, 0);
    cudaStreamWaitEvent(s_side, ev_fork, 0);
    route_kernel<<<1, 256, 0, s_side>>>(topk);
    cudaEventRecord(ev_route, s_side);
    {
        int n42 = NE * HID * INT_DIM / 4;
        cvt_kernel<<<4736, 256, 0, s_side>>>(downW, w2p, n42);
    }
    zero_kernel<<<1184, 256, 0, s_side>>>(out, NTOK * HID / 4);
    cudaEventRecord(ev_join, s_side);

    // main stream: hid + w1 conversion, then GEMM1 (needs route), then GEMM2 (needs w2+zero)
    {
        int n4h = NTOK * HID / 4;
        cvt_kernel<<<1184, 256>>>(hidden, hid16p, n4h);
        int n41 = NE * N1 * HID / 4;
        cvt_kernel<<<4736, 256>>>(gup, w1p, n41);
    }
    cudaStreamWaitEvent(0, ev_route, 0);
    moe_mma<1><<<dim3(INT_DIM / 64, TK / BLKM, NE), 512, SMEM_DYN>>>(wts, out);
    cudaStreamWaitEvent(0, ev_join, 0);
    moe_mma<2><<<dim3((HID / 128) * 2, TK / BLKM, NE), 512, SMEM_DYN>>>(wts, out);
}

// round 11
// speedup vs baseline: 1.0259x; 1.0259x over previous
#include <cuda_runtime.h>
#include <cuda_fp16.h>
#include <cstdint>

#define NE 8
#define HID 2048
#define INT_DIM 2048
#define NTOK 4096
#define TK 8192
#define N1 4096

#define BKH 64            // k-halves per stage (128B rows)
#define BLKM 256          // rows per CTA
#define LDS_H 72          // halves per smem row (64 data + 8 pad = 144B)
#define A_TILE_BYTES (BLKM * LDS_H * 2)     // 36864
#define B_OFF        A_TILE_BYTES
#define B_TILE_BYTES (128 * LDS_H * 2)      // 18432
#define STAGE_BYTES  (A_TILE_BYTES + B_TILE_BYTES)  // 55296
#define NSTAGE 4
#define SMEM_DYN (NSTAGE * STAGE_BYTES)     // 221184

// ---------------- scratch ----------------
__device__ int    d_off[NE + 1];
__device__ int    d_row_slot[TK];
__device__ int    d_row_of_slot[TK];
__device__ __half d_hid16[(size_t)NTOK * HID];
__device__ __half d_w1h[(size_t)NE * N1 * HID];
__device__ __half d_w2h[(size_t)NE * HID * INT_DIM];
__device__ __half d_act16[(size_t)TK * INT_DIM];

// ---------------- helpers ----------------
__device__ __forceinline__ uint32_t smem_u32(const void* p) {
    uint32_t a;
    asm("{ .reg .u64 t; cvta.to.shared.u64 t, %1; cvt.u32.u64 %0, t; }" : "=r"(a) : "l"(p));
    return a;
}
__device__ __forceinline__ void ldsm4(uint32_t& r0, uint32_t& r1, uint32_t& r2, uint32_t& r3,
                                      uint32_t addr) {
    asm volatile("ldmatrix.sync.aligned.m8n8.x4.shared.b16 {%0,%1,%2,%3}, [%4];"
                 : "=r"(r0), "=r"(r1), "=r"(r2), "=r"(r3) : "r"(addr));
}
__device__ __forceinline__ void mma16816(float& c0, float& c1, float& c2, float& c3,
                                         uint32_t a0, uint32_t a1, uint32_t a2, uint32_t a3,
                                         uint32_t b0, uint32_t b1) {
    asm volatile("mma.sync.aligned.m16n8k16.row.col.f32.f16.f16.f32 "
                 "{%0,%1,%2,%3}, {%4,%5,%6,%7}, {%8,%9}, {%0,%1,%2,%3};"
                 : "+f"(c0), "+f"(c1), "+f"(c2), "+f"(c3)
                 : "r"(a0), "r"(a1), "r"(a2), "r"(a3), "r"(b0), "r"(b1));
}
__device__ __forceinline__ void cp16(uint32_t dst, const void* src, bool pred) {
    int sz = pred ? 16 : 0;
    asm volatile("cp.async.cg.shared.global [%0], [%1], 16, %2;"
                 :: "r"(dst), "l"(src), "r"(sz) : "memory");
}
#define CP_COMMIT() asm volatile("cp.async.commit_group;" ::: "memory")
#define CP_WAIT(n)  asm volatile("cp.async.wait_group %0;" :: "n"(n) : "memory")

// ---------------- fp32 -> fp16 conversion (streaming reads) ----------------
__global__ void cvt_kernel(const float* __restrict__ src, __half* __restrict__ dst, int n4) {
    int i = blockIdx.x * blockDim.x + threadIdx.x;
    int stride = gridDim.x * blockDim.x;
    for (; i < n4; i += stride) {
        float4 v = __ldcs((const float4*)(src + (size_t)i * 4));
        __half2 h01 = __floats2half2_rn(v.x, v.y);
        __half2 h23 = __floats2half2_rn(v.z, v.w);
        uint2 u;
        u.x = *(uint32_t*)&h01;
        u.y = *(uint32_t*)&h23;
        *(uint2*)(dst + (size_t)i * 4) = u;
    }
}

// ---------------- zero output ----------------
__global__ void zero_kernel(float* __restrict__ out, int n4) {
    int i = blockIdx.x * blockDim.x + threadIdx.x;
    int stride = gridDim.x * blockDim.x;
    for (; i < n4; i += stride)
        *(float4*)(out + (size_t)i * 4) = make_float4(0.f, 0.f, 0.f, 0.f);
}

// ---------------- routing ----------------
__global__ void route_kernel(const int* __restrict__ topk) {
    __shared__ int s_cnt[NE];
    __shared__ int s_pos[NE];
    int tid = threadIdx.x;
    if (tid < NE) s_cnt[tid] = 0;
    __syncthreads();
    for (int s = tid; s < TK; s += blockDim.x)
        atomicAdd(&s_cnt[topk[s]], 1);
    __syncthreads();
    if (tid == 0) {
        int a = 0;
        for (int e = 0; e < NE; e++) { d_off[e] = a; s_pos[e] = a; a += s_cnt[e]; }
        d_off[NE] = a;
    }
    __syncthreads();
    for (int s = tid; s < TK; s += blockDim.x) {
        int e = topk[s];
        int r = atomicAdd(&s_pos[e], 1);
        d_row_slot[r]    = s;
        d_row_of_slot[s] = r;
    }
}

// ---------------- grouped GEMM: cp.async 4-stage, all-fp16 operands ----------------
// PHASE 1: A = d_hid16 (gathered); B rows = [gate nt..nt+63 | up nt..nt+63] of d_w1h
//          epilogue: SwiGLU * routing weight -> d_act16 (64 act cols per block)
// PHASE 2: A = d_act16; B = d_w2h rows nt..nt+127; epilogue: atomicAdd into out
template <int PHASE>
__global__ __launch_bounds__(512, 1) void moe_mma(const float* __restrict__ wts,
                                                  float* __restrict__ out) {
    const int e   = blockIdx.z;
    const int off = d_off[e];
    const int cnt = d_off[e + 1] - off;
    const int rt  = blockIdx.y * BLKM;
    if (rt >= cnt) return;
    const int nt = blockIdx.x * (PHASE == 1 ? 64 : 128);

    extern __shared__ __align__(16) char smem_raw[];
    const uint32_t sb = smem_u32(smem_raw);

    const int tid  = threadIdx.x;
    const int wid  = tid >> 5, lane = tid & 31;
    const int wm   = wid >> 2;
    const int wn   = wid & 3;

    const int K = HID;
    const int NCH = K / BKH;  // 32
    const __half* Wh = (PHASE == 1)
        ? d_w1h + (size_t)e * N1 * HID
        : d_w2h + (size_t)e * HID * INT_DIM;

    // ---- cp.async assignments ----
    const __half* aSrc[4]; bool aval[4]; uint32_t aDst[4];
    #pragma unroll
    for (int i = 0; i < 4; i++) {
        int chunk = i * 512 + tid;
        int row = chunk >> 3, c16 = chunk & 7;
        int rg = rt + row;
        aval[i] = rg < cnt;
        aDst[i] = (uint32_t)(row * (LDS_H * 2) + c16 * 16);
        if (PHASE == 1) {
            int tok = aval[i] ? (d_row_slot[off + rg] >> 1) : 0;
            aSrc[i] = d_hid16 + (size_t)tok * HID + c16 * 8;
        } else {
            aSrc[i] = d_act16 + (size_t)(off + (aval[i] ? rg : 0)) * INT_DIM + c16 * 8;
        }
    }
    const __half* bSrc[2]; uint32_t bDst[2];
    #pragma unroll
    for (int i = 0; i < 2; i++) {
        int chunk = i * 512 + tid;
        int row = chunk >> 3, c16 = chunk & 7;
        int grow;
        if (PHASE == 1) grow = (row < 64) ? (nt + row) : (INT_DIM + nt + (row - 64));
        else            grow = nt + row;
        bDst[i] = (uint32_t)(B_OFF + row * (LDS_H * 2) + c16 * 16);
        bSrc[i] = Wh + (size_t)grow * K + c16 * 8;
    }

    // ldmatrix byte offsets (kk = 0)
    int aOff[4], bOff[2];
    #pragma unroll
    for (int mi = 0; mi < 4; mi++)
        aOff[mi] = ((wm * 64 + mi * 16 + (lane & 15)) * LDS_H) * 2 + (lane >> 4) * 16;
    #pragma unroll
    for (int g = 0; g < 2; g++)
        bOff[g] = B_OFF + ((wn * 32 + g * 16 + ((lane >> 4) & 1) * 8 + (lane & 7)) * LDS_H) * 2
                  + ((lane >> 3) & 1) * 16;

    float acc[4][4][4];
    #pragma unroll
    for (int mi = 0; mi < 4; mi++)
        #pragma unroll
        for (int ni = 0; ni < 4; ni++)
            #pragma unroll
            for (int q = 0; q < 4; q++) acc[mi][ni][q] = 0.f;

    #define ISSUE(ks) do {                                              \
        uint32_t _base = sb + ((ks) % NSTAGE) * STAGE_BYTES;            \
        int _ko = (ks) * BKH;                                           \
        _Pragma("unroll")                                               \
        for (int _i = 0; _i < 4; _i++)                                  \
            cp16(_base + aDst[_i], aSrc[_i] + _ko, aval[_i]);           \
        _Pragma("unroll")                                               \
        for (int _i = 0; _i < 2; _i++)                                  \
            cp16(_base + bDst[_i], bSrc[_i] + _ko, true);               \
        CP_COMMIT();                                                    \
    } while (0)

    ISSUE(0);
    ISSUE(1);
    ISSUE(2);

    for (int c = 0; c < NCH; c++) {
        CP_WAIT(2);
        __syncthreads();
        if (c + 3 < NCH) ISSUE(c + 3); else CP_COMMIT();

        const uint32_t st = sb + (c % NSTAGE) * STAGE_BYTES;
        #pragma unroll
        for (int kk = 0; kk < 4; kk++) {
            const int kb = kk * 32;
            uint32_t a[4][4], b[4][2];
            #pragma unroll
            for (int mi = 0; mi < 4; mi++)
                ldsm4(a[mi][0], a[mi][1], a[mi][2], a[mi][3], st + aOff[mi] + kb);
            #pragma unroll
            for (int g = 0; g < 2; g++)
                ldsm4(b[2 * g][0], b[2 * g][1], b[2 * g + 1][0], b[2 * g + 1][1],
                      st + bOff[g] + kb);
            #pragma unroll
            for (int mi = 0; mi < 4; mi++)
                #pragma unroll
                for (int ni = 0; ni < 4; ni++)
                    mma16816(acc[mi][ni][0], acc[mi][ni][1], acc[mi][ni][2], acc[mi][ni][3],
                             a[mi][0], a[mi][1], a[mi][2], a[mi][3],
                             b[ni][0], b[ni][1]);
        }
    }
    #undef ISSUE
    CP_WAIT(0);
    __syncthreads();  // all reads done before smem reuse in epilogue

    // ---- epilogue ----
    if (PHASE == 1) {
        float* exch = (float*)smem_raw;  // 256 x 66 fp32 = 67584 <= SMEM_DYN
        const int EP = 66;
        if (wn < 2) {
            #pragma unroll
            for (int mi = 0; mi < 4; mi++) {
                int row0 = wm * 64 + mi * 16 + (lane >> 2);
                #pragma unroll
                for (int ni = 0; ni < 4; ni++) {
                    int col = wn * 32 + ni * 8 + 2 * (lane & 3);
                    float g0 = acc[mi][ni][0], g1 = acc[mi][ni][1];
                    float g2 = acc[mi][ni][2], g3 = acc[mi][ni][3];
                    exch[row0 * EP + col]           = g0 / (1.f + __expf(-g0));
                    exch[row0 * EP + col + 1]       = g1 / (1.f + __expf(-g1));
                    exch[(row0 + 8) * EP + col]     = g2 / (1.f + __expf(-g2));
                    exch[(row0 + 8) * EP + col + 1] = g3 / (1.f + __expf(-g3));
                }
            }
        }
        __syncthreads();
        if (wn >= 2) {
            #pragma unroll
            for (int mi = 0; mi < 4; mi++) {
                int row0 = wm * 64 + mi * 16 + (lane >> 2);
                int rg0 = rt + row0, rg1 = rg0 + 8;
                bool v0 = rg0 < cnt, v1 = rg1 < cnt;
                float w0 = v0 ? wts[d_row_slot[off + rg0]] : 0.f;
                float w1 = v1 ? wts[d_row_slot[off + rg1]] : 0.f;
                #pragma unroll
                for (int ni = 0; ni < 4; ni++) {
                    int col = (wn - 2) * 32 + ni * 8 + 2 * (lane & 3);
                    float s0 = exch[row0 * EP + col];
                    float s1 = exch[row0 * EP + col + 1];
                    float s2 = exch[(row0 + 8) * EP + col];
                    float s3 = exch[(row0 + 8) * EP + col + 1];
                    float a0 = s0 * acc[mi][ni][0] * w0;
                    float a1 = s1 * acc[mi][ni][1] * w0;
                    float a2 = s2 * acc[mi][ni][2] * w1;
                    float a3 = s3 * acc[mi][ni][3] * w1;
                    if (v0) {
                        __half2 h = __floats2half2_rn(a0, a1);
                        *(uint32_t*)&d_act16[(size_t)(off + rg0) * INT_DIM + nt + col] =
                            *(uint32_t*)&h;
                    }
                    if (v1) {
                        __half2 h = __floats2half2_rn(a2, a3);
                        *(uint32_t*)&d_act16[(size_t)(off + rg1) * INT_DIM + nt + col] =
                            *(uint32_t*)&h;
                    }
                }
            }
        }
    } else {
        // atomicAdd weighted (weights pre-applied in act) rows into out[token]
        #pragma unroll
        for (int mi = 0; mi < 4; mi++) {
            int row0 = wm * 64 + mi * 16 + (lane >> 2);
            int rg0 = rt + row0, rg1 = rg0 + 8;
            bool v0 = rg0 < cnt, v1 = rg1 < cnt;
            int t0 = v0 ? (d_row_slot[off + rg0] >> 1) : 0;
            int t1 = v1 ? (d_row_slot[off + rg1] >> 1) : 0;
            #pragma unroll
            for (int ni = 0; ni < 4; ni++) {
                int col = nt + wn * 32 + ni * 8 + 2 * (lane & 3);
                if (v0) {
                    float* p = out + (size_t)t0 * HID + col;
                    atomicAdd(p,     acc[mi][ni][0]);
                    atomicAdd(p + 1, acc[mi][ni][1]);
                }
                if (v1) {
                    float* p = out + (size_t)t1 * HID + col;
                    atomicAdd(p,     acc[mi][ni][2]);
                    atomicAdd(p + 1, acc[mi][ni][3]);
                }
            }
        }
    }
}

// ---------------- launcher ----------------
extern "C" void kernel_launch(void* const* d_in, const int* in_sizes, int n_in,
                              void* d_out, int out_size) {
    const float* hidden = (const float*)d_in[0];
    const int*   topk   = (const int*)  d_in[1];
    const float* wts    = (const float*)d_in[2];
    const float* gup    = (const float*)d_in[3];
    const float* downW  = (const float*)d_in[4];
    float* out = (float*)d_out;

    cudaFuncSetAttribute(moe_mma<1>, cudaFuncAttributeMaxDynamicSharedMemorySize, SMEM_DYN);
    cudaFuncSetAttribute(moe_mma<2>, cudaFuncAttributeMaxDynamicSharedMemorySize, SMEM_DYN);

    __half* hid16p; cudaGetSymbolAddress((void**)&hid16p, d_hid16);
    __half* w1p;    cudaGetSymbolAddress((void**)&w1p,    d_w1h);
    __half* w2p;    cudaGetSymbolAddress((void**)&w2p,    d_w2h);

    // one-time side stream + events (host resources only; no device memory)
    static cudaStream_t s_side = nullptr;
    static cudaEvent_t ev_fork = nullptr, ev_join = nullptr;
    if (s_side == nullptr) {
        cudaStreamCreateWithFlags(&s_side, cudaStreamNonBlocking);
        cudaEventCreateWithFlags(&ev_fork, cudaEventDisableTiming);
        cudaEventCreateWithFlags(&ev_join, cudaEventDisableTiming);
    }

    // main stream: route + the cvts GEMM1 needs (serial — all DRAM-bound anyway)
    route_kernel<<<1, 256>>>(topk);
    {
        int n4h = NTOK * HID / 4;
        cvt_kernel<<<1184, 256>>>(hidden, hid16p, n4h);
        int n41 = NE * N1 * HID / 4;
        cvt_kernel<<<4736, 256>>>(gup, w1p, n41);
    }

    // fork AFTER main-stream memory phase: side work runs under compute-bound GEMM1
    cudaEventRecord(ev_fork, 0);
    cudaStreamWaitEvent(s_side, ev_fork, 0);
    {
        int n42 = NE * HID * INT_DIM / 4;
        cvt_kernel<<<4736, 256, 0, s_side>>>(downW, w2p, n42);
    }
    zero_kernel<<<1184, 256, 0, s_side>>>(out, NTOK * HID / 4);
    cudaEventRecord(ev_join, s_side);

    moe_mma<1><<<dim3(INT_DIM / 64, TK / BLKM, NE), 512, SMEM_DYN>>>(wts, out);
    cudaStreamWaitEvent(0, ev_join, 0);
    moe_mma<2><<<dim3(HID / 128, TK / BLKM, NE), 512, SMEM_DYN>>>(wts, out);
}

// round 13
// speedup vs baseline: 1.0380x; 1.0118x over previous
#include <cuda_runtime.h>
#include <cuda_fp16.h>
#include <cstdint>

#define NE 8
#define HID 2048
#define INT_DIM 2048
#define NTOK 4096
#define TK 8192
#define N1 4096

#define BKH 64            // k-halves per stage (128B rows)
#define BLKM 256          // rows per CTA
#define LDS_H 72          // halves per smem row (64 data + 8 pad = 144B)
#define A_TILE_BYTES (BLKM * LDS_H * 2)     // 36864
#define B_OFF        A_TILE_BYTES
#define B_TILE_BYTES (128 * LDS_H * 2)      // 18432
#define STAGE_BYTES  (A_TILE_BYTES + B_TILE_BYTES)  // 55296
#define NSTAGE 4
#define SMEM_DYN (NSTAGE * STAGE_BYTES)     // 221184

// ---------------- scratch ----------------
__device__ int    d_off[NE + 1];
__device__ int    d_row_slot[TK];
__device__ int    d_row_of_slot[TK];
__device__ __half d_hid16[(size_t)NTOK * HID];
__device__ __half d_w1h[(size_t)NE * N1 * HID];
__device__ __half d_w2h[(size_t)NE * HID * INT_DIM];
__device__ __half d_act16[(size_t)TK * INT_DIM];

// ---------------- helpers ----------------
__device__ __forceinline__ uint32_t smem_u32(const void* p) {
    uint32_t a;
    asm("{ .reg .u64 t; cvta.to.shared.u64 t, %1; cvt.u32.u64 %0, t; }" : "=r"(a) : "l"(p));
    return a;
}
__device__ __forceinline__ void ldsm4(uint32_t& r0, uint32_t& r1, uint32_t& r2, uint32_t& r3,
                                      uint32_t addr) {
    asm volatile("ldmatrix.sync.aligned.m8n8.x4.shared.b16 {%0,%1,%2,%3}, [%4];"
                 : "=r"(r0), "=r"(r1), "=r"(r2), "=r"(r3) : "r"(addr));
}
__device__ __forceinline__ void mma16816(float& c0, float& c1, float& c2, float& c3,
                                         uint32_t a0, uint32_t a1, uint32_t a2, uint32_t a3,
                                         uint32_t b0, uint32_t b1) {
    asm volatile("mma.sync.aligned.m16n8k16.row.col.f32.f16.f16.f32 "
                 "{%0,%1,%2,%3}, {%4,%5,%6,%7}, {%8,%9}, {%0,%1,%2,%3};"
                 : "+f"(c0), "+f"(c1), "+f"(c2), "+f"(c3)
                 : "r"(a0), "r"(a1), "r"(a2), "r"(a3), "r"(b0), "r"(b1));
}
__device__ __forceinline__ void cp16(uint32_t dst, const void* src, bool pred) {
    int sz = pred ? 16 : 0;
    asm volatile("cp.async.cg.shared.global [%0], [%1], 16, %2;"
                 :: "r"(dst), "l"(src), "r"(sz) : "memory");
}
#define CP_COMMIT() asm volatile("cp.async.commit_group;" ::: "memory")
#define CP_WAIT(n)  asm volatile("cp.async.wait_group %0;" :: "n"(n) : "memory")

// ---------------- fp32 -> fp16 conversion (streaming reads) ----------------
__global__ void cvt_kernel(const float* __restrict__ src, __half* __restrict__ dst, int n4) {
    int i = blockIdx.x * blockDim.x + threadIdx.x;
    int stride = gridDim.x * blockDim.x;
    for (; i < n4; i += stride) {
        float4 v = __ldcs((const float4*)(src + (size_t)i * 4));
        __half2 h01 = __floats2half2_rn(v.x, v.y);
        __half2 h23 = __floats2half2_rn(v.z, v.w);
        uint2 u;
        u.x = *(uint32_t*)&h01;
        u.y = *(uint32_t*)&h23;
        *(uint2*)(dst + (size_t)i * 4) = u;
    }
}

// Convert the half of w1 needed by GEMM1 x-tiles [part*16, part*16+16):
// rows [part*1024, part*1024+1024) of BOTH the gate block and the up block, per expert.
__global__ void cvt_w1_part_kernel(const float* __restrict__ src, __half* __restrict__ dst,
                                   int part) {
    const int CH4 = 1024 * HID / 4;        // float4s per (expert, half-block) range
    const int TOT = NE * 2 * CH4;
    int i = blockIdx.x * blockDim.x + threadIdx.x;
    int stride = gridDim.x * blockDim.x;
    for (; i < TOT; i += stride) {
        int e    = i / (2 * CH4);
        int rem  = i % (2 * CH4);
        int half = rem / CH4;
        int r4   = rem % CH4;
        size_t o4 = (size_t)e * (N1 * HID / 4) + (size_t)half * (INT_DIM * HID / 4)
                  + (size_t)part * CH4 + r4;
        float4 v = __ldcs((const float4*)(src + o4 * 4));
        __half2 h01 = __floats2half2_rn(v.x, v.y);
        __half2 h23 = __floats2half2_rn(v.z, v.w);
        uint2 u;
        u.x = *(uint32_t*)&h01;
        u.y = *(uint32_t*)&h23;
        *(uint2*)(dst + o4 * 4) = u;
    }
}

// ---------------- zero output ----------------
__global__ void zero_kernel(float* __restrict__ out, int n4) {
    int i = blockIdx.x * blockDim.x + threadIdx.x;
    int stride = gridDim.x * blockDim.x;
    for (; i < n4; i += stride)
        *(float4*)(out + (size_t)i * 4) = make_float4(0.f, 0.f, 0.f, 0.f);
}

// ---------------- routing ----------------
__global__ void route_kernel(const int* __restrict__ topk) {
    __shared__ int s_cnt[NE];
    __shared__ int s_pos[NE];
    int tid = threadIdx.x;
    if (tid < NE) s_cnt[tid] = 0;
    __syncthreads();
    for (int s = tid; s < TK; s += blockDim.x)
        atomicAdd(&s_cnt[topk[s]], 1);
    __syncthreads();
    if (tid == 0) {
        int a = 0;
        for (int e = 0; e < NE; e++) { d_off[e] = a; s_pos[e] = a; a += s_cnt[e]; }
        d_off[NE] = a;
    }
    __syncthreads();
    for (int s = tid; s < TK; s += blockDim.x) {
        int e = topk[s];
        int r = atomicAdd(&s_pos[e], 1);
        d_row_slot[r]    = s;
        d_row_of_slot[s] = r;
    }
}

// ---------------- grouped GEMM: cp.async 4-stage, all-fp16 operands ----------------
// PHASE 1: A = d_hid16 (gathered); B rows = [gate nt..nt+63 | up nt..nt+63] of d_w1h
//          epilogue: SwiGLU * routing weight -> d_act16 (64 act cols per block)
// PHASE 2: A = d_act16; B = d_w2h rows nt..nt+127; epilogue: atomicAdd into out
template <int PHASE>
__global__ __launch_bounds__(512, 1) void moe_mma(const float* __restrict__ wts,
                                                  float* __restrict__ out, int xoff) {
    const int e   = blockIdx.z;
    const int off = d_off[e];
    const int cnt = d_off[e + 1] - off;
    const int rt  = blockIdx.y * BLKM;
    if (rt >= cnt) return;
    const int nt = (blockIdx.x + xoff) * (PHASE == 1 ? 64 : 128);

    extern __shared__ __align__(16) char smem_raw[];
    const uint32_t sb = smem_u32(smem_raw);

    const int tid  = threadIdx.x;
    const int wid  = tid >> 5, lane = tid & 31;
    const int wm   = wid >> 2;
    const int wn   = wid & 3;

    const int K = HID;
    const int NCH = K / BKH;  // 32
    const __half* Wh = (PHASE == 1)
        ? d_w1h + (size_t)e * N1 * HID
        : d_w2h + (size_t)e * HID * INT_DIM;

    // ---- cp.async assignments ----
    const __half* aSrc[4]; bool aval[4]; uint32_t aDst[4];
    #pragma unroll
    for (int i = 0; i < 4; i++) {
        int chunk = i * 512 + tid;
        int row = chunk >> 3, c16 = chunk & 7;
        int rg = rt + row;
        aval[i] = rg < cnt;
        aDst[i] = (uint32_t)(row * (LDS_H * 2) + c16 * 16);
        if (PHASE == 1) {
            int tok = aval[i] ? (d_row_slot[off + rg] >> 1) : 0;
            aSrc[i] = d_hid16 + (size_t)tok * HID + c16 * 8;
        } else {
            aSrc[i] = d_act16 + (size_t)(off + (aval[i] ? rg : 0)) * INT_DIM + c16 * 8;
        }
    }
    const __half* bSrc[2]; uint32_t bDst[2];
    #pragma unroll
    for (int i = 0; i < 2; i++) {
        int chunk = i * 512 + tid;
        int row = chunk >> 3, c16 = chunk & 7;
        int grow;
        if (PHASE == 1) grow = (row < 64) ? (nt + row) : (INT_DIM + nt + (row - 64));
        else            grow = nt + row;
        bDst[i] = (uint32_t)(B_OFF + row * (LDS_H * 2) + c16 * 16);
        bSrc[i] = Wh + (size_t)grow * K + c16 * 8;
    }

    // ldmatrix byte offsets (kk = 0)
    int aOff[4], bOff[2];
    #pragma unroll
    for (int mi = 0; mi < 4; mi++)
        aOff[mi] = ((wm * 64 + mi * 16 + (lane & 15)) * LDS_H) * 2 + (lane >> 4) * 16;
    #pragma unroll
    for (int g = 0; g < 2; g++)
        bOff[g] = B_OFF + ((wn * 32 + g * 16 + ((lane >> 4) & 1) * 8 + (lane & 7)) * LDS_H) * 2
                  + ((lane >> 3) & 1) * 16;

    float acc[4][4][4];
    #pragma unroll
    for (int mi = 0; mi < 4; mi++)
        #pragma unroll
        for (int ni = 0; ni < 4; ni++)
            #pragma unroll
            for (int q = 0; q < 4; q++) acc[mi][ni][q] = 0.f;

    #define ISSUE(ks) do {                                              \
        uint32_t _base = sb + ((ks) % NSTAGE) * STAGE_BYTES;            \
        int _ko = (ks) * BKH;                                           \
        _Pragma("unroll")                                               \
        for (int _i = 0; _i < 4; _i++)                                  \
            cp16(_base + aDst[_i], aSrc[_i] + _ko, aval[_i]);           \
        _Pragma("unroll")                                               \
        for (int _i = 0; _i < 2; _i++)                                  \
            cp16(_base + bDst[_i], bSrc[_i] + _ko, true);               \
        CP_COMMIT();                                                    \
    } while (0)

    ISSUE(0);
    ISSUE(1);
    ISSUE(2);

    for (int c = 0; c < NCH; c++) {
        CP_WAIT(2);
        __syncthreads();
        if (c + 3 < NCH) ISSUE(c + 3); else CP_COMMIT();

        const uint32_t st = sb + (c % NSTAGE) * STAGE_BYTES;
        #pragma unroll
        for (int kk = 0; kk < 4; kk++) {
            const int kb = kk * 32;
            uint32_t a[4][4], b[4][2];
            #pragma unroll
            for (int mi = 0; mi < 4; mi++)
                ldsm4(a[mi][0], a[mi][1], a[mi][2], a[mi][3], st + aOff[mi] + kb);
            #pragma unroll
            for (int g = 0; g < 2; g++)
                ldsm4(b[2 * g][0], b[2 * g][1], b[2 * g + 1][0], b[2 * g + 1][1],
                      st + bOff[g] + kb);
            #pragma unroll
            for (int mi = 0; mi < 4; mi++)
                #pragma unroll
                for (int ni = 0; ni < 4; ni++)
                    mma16816(acc[mi][ni][0], acc[mi][ni][1], acc[mi][ni][2], acc[mi][ni][3],
                             a[mi][0], a[mi][1], a[mi][2], a[mi][3],
                             b[ni][0], b[ni][1]);
        }
    }
    #undef ISSUE
    CP_WAIT(0);
    __syncthreads();  // all reads done before smem reuse in epilogue

    // ---- epilogue ----
    if (PHASE == 1) {
        float* exch = (float*)smem_raw;  // 256 x 66 fp32 = 67584 <= SMEM_DYN
        const int EP = 66;
        if (wn < 2) {
            #pragma unroll
            for (int mi = 0; mi < 4; mi++) {
                int row0 = wm * 64 + mi * 16 + (lane >> 2);
                #pragma unroll
                for (int ni = 0; ni < 4; ni++) {
                    int col = wn * 32 + ni * 8 + 2 * (lane & 3);
                    float g0 = acc[mi][ni][0], g1 = acc[mi][ni][1];
                    float g2 = acc[mi][ni][2], g3 = acc[mi][ni][3];
                    exch[row0 * EP + col]           = g0 / (1.f + __expf(-g0));
                    exch[row0 * EP + col + 1]       = g1 / (1.f + __expf(-g1));
                    exch[(row0 + 8) * EP + col]     = g2 / (1.f + __expf(-g2));
                    exch[(row0 + 8) * EP + col + 1] = g3 / (1.f + __expf(-g3));
                }
            }
        }
        __syncthreads();
        if (wn >= 2) {
            #pragma unroll
            for (int mi = 0; mi < 4; mi++) {
                int row0 = wm * 64 + mi * 16 + (lane >> 2);
                int rg0 = rt + row0, rg1 = rg0 + 8;
                bool v0 = rg0 < cnt, v1 = rg1 < cnt;
                float w0 = v0 ? wts[d_row_slot[off + rg0]] : 0.f;
                float w1 = v1 ? wts[d_row_slot[off + rg1]] : 0.f;
                #pragma unroll
                for (int ni = 0; ni < 4; ni++) {
                    int col = (wn - 2) * 32 + ni * 8 + 2 * (lane & 3);
                    float s0 = exch[row0 * EP + col];
                    float s1 = exch[row0 * EP + col + 1];
                    float s2 = exch[(row0 + 8) * EP + col];
                    float s3 = exch[(row0 + 8) * EP + col + 1];
                    float a0 = s0 * acc[mi][ni][0] * w0;
                    float a1 = s1 * acc[mi][ni][1] * w0;
                    float a2 = s2 * acc[mi][ni][2] * w1;
                    float a3 = s3 * acc[mi][ni][3] * w1;
                    if (v0) {
                        __half2 h = __floats2half2_rn(a0, a1);
                        *(uint32_t*)&d_act16[(size_t)(off + rg0) * INT_DIM + nt + col] =
                            *(uint32_t*)&h;
                    }
                    if (v1) {
                        __half2 h = __floats2half2_rn(a2, a3);
                        *(uint32_t*)&d_act16[(size_t)(off + rg1) * INT_DIM + nt + col] =
                            *(uint32_t*)&h;
                    }
                }
            }
        }
    } else {
        // atomicAdd weighted (weights pre-applied in act) rows into out[token]
        #pragma unroll
        for (int mi = 0; mi < 4; mi++) {
            int row0 = wm * 64 + mi * 16 + (lane >> 2);
            int rg0 = rt + row0, rg1 = rg0 + 8;
            bool v0 = rg0 < cnt, v1 = rg1 < cnt;
            int t0 = v0 ? (d_row_slot[off + rg0] >> 1) : 0;
            int t1 = v1 ? (d_row_slot[off + rg1] >> 1) : 0;
            #pragma unroll
            for (int ni = 0; ni < 4; ni++) {
                int col = nt + wn * 32 + ni * 8 + 2 * (lane & 3);
                if (v0) {
                    float* p = out + (size_t)t0 * HID + col;
                    atomicAdd(p,     acc[mi][ni][0]);
                    atomicAdd(p + 1, acc[mi][ni][1]);
                }
                if (v1) {
                    float* p = out + (size_t)t1 * HID + col;
                    atomicAdd(p,     acc[mi][ni][2]);
                    atomicAdd(p + 1, acc[mi][ni][3]);
                }
            }
        }
    }
}

// ---------------- launcher ----------------
extern "C" void kernel_launch(void* const* d_in, const int* in_sizes, int n_in,
                              void* d_out, int out_size) {
    const float* hidden = (const float*)d_in[0];
    const int*   topk   = (const int*)  d_in[1];
    const float* wts    = (const float*)d_in[2];
    const float* gup    = (const float*)d_in[3];
    const float* downW  = (const float*)d_in[4];
    float* out = (float*)d_out;

    cudaFuncSetAttribute(moe_mma<1>, cudaFuncAttributeMaxDynamicSharedMemorySize, SMEM_DYN);
    cudaFuncSetAttribute(moe_mma<2>, cudaFuncAttributeMaxDynamicSharedMemorySize, SMEM_DYN);

    __half* hid16p; cudaGetSymbolAddress((void**)&hid16p, d_hid16);
    __half* w1p;    cudaGetSymbolAddress((void**)&w1p,    d_w1h);
    __half* w2p;    cudaGetSymbolAddress((void**)&w2p,    d_w2h);

    // one-time side stream + events (host resources only; no device memory)
    static cudaStream_t s_side = nullptr;
    static cudaEvent_t ev_fork = nullptr, ev_w1b = nullptr, ev_join = nullptr;
    if (s_side == nullptr) {
        cudaStreamCreateWithFlags(&s_side, cudaStreamNonBlocking);
        cudaEventCreateWithFlags(&ev_fork, cudaEventDisableTiming);
        cudaEventCreateWithFlags(&ev_w1b,  cudaEventDisableTiming);
        cudaEventCreateWithFlags(&ev_join, cudaEventDisableTiming);
    }

    // main stream: route + cvt(hidden) + cvt(w1 part0) — the minimum GEMM1a needs
    route_kernel<<<1, 256>>>(topk);
    {
        int n4h = NTOK * HID / 4;
        cvt_kernel<<<1184, 256>>>(hidden, hid16p, n4h);
    }
    cvt_w1_part_kernel<<<2368, 256>>>(gup, w1p, 0);

    // fork: side stream does w1 part1 (feeds GEMM1b), then w2 + zero (feed GEMM2),
    // all hidden under the compute-bound GEMM1a/GEMM1b on the main stream.
    cudaEventRecord(ev_fork, 0);
    cudaStreamWaitEvent(s_side, ev_fork, 0);
    cvt_w1_part_kernel<<<2368, 256, 0, s_side>>>(gup, w1p, 1);
    cudaEventRecord(ev_w1b, s_side);
    {
        int n42 = NE * HID * INT_DIM / 4;
        cvt_kernel<<<4736, 256, 0, s_side>>>(downW, w2p, n42);
    }
    zero_kernel<<<1184, 256, 0, s_side>>>(out, NTOK * HID / 4);
    cudaEventRecord(ev_join, s_side);

    // GEMM1 in two x-halves; half b waits only on its weights
    moe_mma<1><<<dim3(16, TK / BLKM, NE), 512, SMEM_DYN>>>(wts, out, 0);
    cudaStreamWaitEvent(0, ev_w1b, 0);
    moe_mma<1><<<dim3(16, TK / BLKM, NE), 512, SMEM_DYN>>>(wts, out, 16);
    cudaStreamWaitEvent(0, ev_join, 0);
    moe_mma<2><<<dim3(HID / 128, TK / BLKM, NE), 512, SMEM_DYN>>>(wts, out, 0);
}